// round 14
// baseline (speedup 1.0000x reference)
#include <cuda_runtime.h>
#include <math.h>

#define SS 4096
#define BB 128
#define HH 128
#define NCH 16
#define ROWS_PER_CHUNK (SS/NCH)   // 256 rows per block, 32 per warp

// scratch (no allocation allowed)
__device__ float g_Mp[NCH*BB];
__device__ float g_Lp[NCH*BB];
__device__ int   g_cnt[BB];       // zero-init at load; reset by last block
__device__ float g_out_scr[BB*HH];
__device__ float g_w_scr[SS*BB];

// array-halving combine: after this, lanes with (lane&off)==0 hold a's
// cross-half partial, lanes with bit set hold b's.
__device__ __forceinline__ float comb(float a, float b, int off, int lane) {
    float keep = (lane & off) ? b : a;
    float send = (lane & off) ? a : b;
    return keep + __shfl_xor_sync(0xffffffffu, send, off);
}

// ---------------------------------------------------------------------------
// coalesced zero of w (2 MB) — cheap, keeps scattered stores out of the
// streaming kernel. Ordered before fused_kernel on the stream.
// ---------------------------------------------------------------------------
__global__ void zero_w_kernel(float4* __restrict__ w) {
    int i = blockIdx.x*blockDim.x + threadIdx.x;
    w[i] = make_float4(0.f, 0.f, 0.f, 0.f);
}

__global__ void __launch_bounds__(256)
fused_kernel(const float* __restrict__ e,
             const float* __restrict__ d,
             const float* __restrict__ Wa,
             const float* __restrict__ Wp,
             const float* __restrict__ vp,
             const float* __restrict__ Wc,
             float* __restrict__ out,
             float* __restrict__ wout) {
    int chunk = blockIdx.x, b = blockIdx.y;
    int t = threadIdx.x;
    int warp = t >> 5, lane = t & 31;

    __shared__ float dsh[HH];
    __shared__ float qsh[HH];
    __shared__ float pacc[2*HH];
    __shared__ float sm[8], sl[8];
    __shared__ float esh[5][HH];
    __shared__ float x[2*HH];
    __shared__ float scr[5];
    __shared__ float wvals[5];
    __shared__ float ML[3];
    __shared__ int islast;

    // ---- issue group-0 e loads FIRST (latency covers q GEMV) ----
    int R0 = chunk*ROWS_PER_CHUNK + warp*32;
    const float* ebase = e + ((size_t)R0*BB + b)*HH + lane*4;
    const size_t rstride = (size_t)BB*HH;
    float4 ev[8];
    #pragma unroll
    for (int j = 0; j < 8; j++)
        ev[j] = __ldcs(reinterpret_cast<const float4*>(ebase + (size_t)j*rstride));

    // ---- in-block q = d[b]@W_a (W_a is L2-resident across all blocks) ----
    if (t < HH) dsh[t] = d[b*HH + t];
    __syncthreads();
    {
        int h = t & 127, half = t >> 7;
        float acc = 0.f;
        #pragma unroll 16
        for (int k = half*64; k < half*64 + 64; k++)
            acc += dsh[k] * Wa[k*HH + h];      // coalesced across h
        pacc[t] = acc;
    }
    __syncthreads();
    if (t < HH) qsh[t] = pacc[t] + pacc[t + HH];
    __syncthreads();
    float4 qv = reinterpret_cast<float4*>(qsh)[lane];

    // ---- stream 4 groups of 8 rows; cheap halving reduction ----
    float rs[4];
    #pragma unroll
    for (int g = 0; g < 4; g++) {
        float s[8];
        #pragma unroll
        for (int j = 0; j < 8; j++)
            s[j] = ev[j].x*qv.x + ev[j].y*qv.y + ev[j].z*qv.z + ev[j].w*qv.w;
        if (g < 3) {
            const float* nb = ebase + (size_t)(g+1)*8*rstride;
            #pragma unroll
            for (int j = 0; j < 8; j++)
                ev[j] = __ldcs(reinterpret_cast<const float4*>(nb + (size_t)j*rstride));
        }
        float r0 = comb(s[0], s[1], 16, lane);
        float r1 = comb(s[2], s[3], 16, lane);
        float r2 = comb(s[4], s[5], 16, lane);
        float r3 = comb(s[6], s[7], 16, lane);
        float u0 = comb(r0, r1, 8, lane);
        float u1 = comb(r2, r3, 8, lane);
        float v0 = comb(u0, u1, 4, lane);
        v0 += __shfl_xor_sync(0xffffffffu, v0, 2);
        v0 += __shfl_xor_sync(0xffffffffu, v0, 1);
        rs[g] = v0;                 // one complete row-score per lane (x4 copies)
    }

    // warp (M, L) over its 32 rows
    float m = fmaxf(fmaxf(rs[0], rs[1]), fmaxf(rs[2], rs[3]));
    #pragma unroll
    for (int off = 16; off; off >>= 1)
        m = fmaxf(m, __shfl_xor_sync(0xffffffffu, m, off));
    float l = 0.f;
    #pragma unroll
    for (int g = 0; g < 4; g++) l += __expf(rs[g] - m);
    #pragma unroll
    for (int off = 16; off; off >>= 1)
        l += __shfl_xor_sync(0xffffffffu, l, off);
    l *= 0.25f;                      // each row counted exactly 4x

    if (lane == 0) { sm[warp] = m; sl[warp] = l; }
    __syncthreads();
    if (t == 0) {
        float M = sm[0];
        #pragma unroll
        for (int c = 1; c < 8; c++) M = fmaxf(M, sm[c]);
        float L = 0.f;
        #pragma unroll
        for (int c = 0; c < 8; c++) L += sl[c]*__expf(sm[c]-M);
        g_Mp[chunk*BB + b] = M;
        g_Lp[chunk*BB + b] = L;
        __threadfence();
        int old = atomicAdd(&g_cnt[b], 1);
        islast = (old == NCH-1);
        if (old == NCH-1) g_cnt[b] = 0;   // reset for next graph replay
    }
    __syncthreads();
    if (!islast) return;

    // ===================== finalize for this b (last block) =================
    __threadfence();

    // p_t = S * sigmoid(tanh(d@W_p)@v_p)  (only 128 blocks run this)
    {
        int h = t & 127, half = t >> 7;
        float acc = 0.f;
        #pragma unroll 16
        for (int k = half*64; k < half*64 + 64; k++)
            acc += dsh[k] * Wp[k*HH + h];
        pacc[t] = acc;
    }
    __syncthreads();
    if (t < HH) pacc[t] = tanhf(pacc[t] + pacc[t + HH]) * vp[t];
    __syncthreads();
    for (int off = HH/2; off > 0; off >>= 1) {
        if (t < off) pacc[t] += pacc[t+off];
        __syncthreads();
    }
    if (t == 0) {
        float z = pacc[0];
        ML[2] = (float)SS / (1.f + expf(-z));
    }

    // global (M, L) over NCH chunk partials (warp 0)
    if (warp == 0) {
        float mm = (lane < NCH) ? ((const volatile float*)g_Mp)[lane*BB + b] : -INFINITY;
        float ll = (lane < NCH) ? ((const volatile float*)g_Lp)[lane*BB + b] : 0.f;
        float M = mm;
        #pragma unroll
        for (int off = 16; off; off >>= 1)
            M = fmaxf(M, __shfl_xor_sync(0xffffffffu, M, off));
        float lc = ll*__expf(mm - M);
        #pragma unroll
        for (int off = 16; off; off >>= 1)
            lc += __shfl_xor_sync(0xffffffffu, lc, off);
        if (lane == 0) { ML[0] = M; ML[1] = lc; }
    }
    __syncthreads();

    // window candidates (uniform per block)
    float pt = ML[2];
    int sf = (int)floorf(pt);
    int cs[5]; int cnt = 0;
    #pragma unroll
    for (int ds = -2; ds <= 2; ds++) {
        int sidx = sf + ds;
        if (sidx < 0 || sidx >= SS) continue;
        float diff = pt - (float)sidx;
        if (fabsf(diff) <= 2.0f) cs[cnt++] = sidx;
    }

    // stage window rows into shared (parallel loads)
    for (int idx = t; idx < cnt*HH; idx += 256) {
        int i = idx >> 7, h = idx & 127;
        esh[i][h] = e[((size_t)cs[i]*BB + b)*HH + h];
    }
    if (t < HH) x[HH + t] = dsh[t];
    __syncthreads();

    // warp i: score of window row i
    if (warp < cnt) {
        float v = 0.f;
        #pragma unroll
        for (int j = 0; j < 4; j++)
            v += esh[warp][lane + 32*j] * qsh[lane + 32*j];
        #pragma unroll
        for (int off = 16; off; off >>= 1)
            v += __shfl_xor_sync(0xffffffffu, v, off);
        if (lane == 0) scr[warp] = v;
    }
    __syncthreads();

    if (t < cnt) {
        float diff = pt - (float)cs[t];
        float a = expf(scr[t] - ML[0]) / ML[1];
        float v = a * expf(-diff*diff*0.5f);
        wvals[t] = v;
        wout[(size_t)cs[t]*BB + b] = v;
    }
    __syncthreads();

    if (t < HH) {
        float ctx = 0.f;
        for (int i = 0; i < cnt; i++)
            ctx += esh[i][t] * wvals[i];
        x[t] = ctx;
    }
    __syncthreads();

    // output GEMM, 2-way k-split
    {
        int h = t & 127, part = t >> 7;
        const float* Wcp = Wc + (size_t)part*HH*HH;
        float acc = 0.f;
        #pragma unroll 16
        for (int k = 0; k < HH; k++)
            acc += x[part*HH + k] * Wcp[k*HH + h];
        pacc[t] = acc;
    }
    __syncthreads();
    if (t < HH)
        out[b*HH + t] = tanhf(pacc[t] + pacc[t + HH]);
}

// ---------------------------------------------------------------------------
extern "C" void kernel_launch(void* const* d_in, const int* in_sizes, int n_in,
                              void* d_out, int out_size) {
    const float* e  = (const float*)d_in[0];
    const float* d  = (const float*)d_in[1];
    const float* Wa = (const float*)d_in[2];
    const float* Wp = (const float*)d_in[3];
    const float* vp = (const float*)d_in[4];
    const float* Wc = (const float*)d_in[5];

    float* base = (float*)d_out;
    float* out_ptr;
    float* w_ptr;
    if (out_size >= BB*HH + SS*BB) {
        out_ptr = base;
        w_ptr   = base + BB*HH;
    } else if (out_size == SS*BB) {
        cudaGetSymbolAddress((void**)&out_ptr, g_out_scr);
        w_ptr = base;
    } else {
        out_ptr = base;
        cudaGetSymbolAddress((void**)&w_ptr, g_w_scr);
    }

    zero_w_kernel<<<(SS*BB/4)/256, 256>>>((float4*)w_ptr);
    fused_kernel<<<dim3(NCH, BB), 256>>>(e, d, Wa, Wp, vp, Wc, out_ptr, w_ptr);
}

// round 15
// speedup vs baseline: 1.0107x; 1.0107x over previous
#include <cuda_runtime.h>
#include <math.h>

#define SS 4096
#define BB 128
#define HH 128
#define NCH 16
#define ROWS_PER_CHUNK (SS/NCH)   // 256 rows per block, 32 per warp

// scratch (no allocation allowed)
__device__ float g_Mp[NCH*BB];
__device__ float g_Lp[NCH*BB];
__device__ int   g_cnt[BB];       // zero-init at load; reset by last block
__device__ float g_out_scr[BB*HH];
__device__ float g_w_scr[SS*BB];

// array-halving combine: after this, lanes with (lane&off)==0 hold a's
// cross-half partial, lanes with bit set hold b's.
__device__ __forceinline__ float comb(float a, float b, int off, int lane) {
    float keep = (lane & off) ? b : a;
    float send = (lane & off) ? a : b;
    return keep + __shfl_xor_sync(0xffffffffu, send, off);
}

__global__ void __launch_bounds__(256, 5)   // cap regs ~51 -> >=40 warps/SM
fused_kernel(const float* __restrict__ e,
             const float* __restrict__ d,
             const float* __restrict__ Wa,
             const float* __restrict__ Wp,
             const float* __restrict__ vp,
             const float* __restrict__ Wc,
             float* __restrict__ out,
             float* __restrict__ wout) {
    int chunk = blockIdx.x, b = blockIdx.y;
    int t = threadIdx.x;
    int warp = t >> 5, lane = t & 31;

    __shared__ float dsh[HH];
    __shared__ float qsh[HH];
    __shared__ float pacc[2*HH];
    __shared__ float sm[8], sl[8];
    __shared__ float esh[5][HH];
    __shared__ float x[2*HH];
    __shared__ float scr[5];
    __shared__ float wvals[5];
    __shared__ float ML[3];
    __shared__ int islast;

    // ---- issue group-0 e loads FIRST (latency covers q GEMV) ----
    int R0 = chunk*ROWS_PER_CHUNK + warp*32;
    const float* ebase = e + ((size_t)R0*BB + b)*HH + lane*4;
    const size_t rstride = (size_t)BB*HH;
    float4 ev[4];
    #pragma unroll
    for (int j = 0; j < 4; j++)
        ev[j] = __ldcs(reinterpret_cast<const float4*>(ebase + (size_t)j*rstride));

    // ---- in-block q = d[b]@W_a (W_a stays L2-resident across 2048 blocks) ----
    if (t < HH) dsh[t] = d[b*HH + t];
    __syncthreads();
    {
        int h = t & 127, half = t >> 7;
        float acc = 0.f;
        #pragma unroll 16
        for (int k = half*64; k < half*64 + 64; k++)
            acc += dsh[k] * Wa[k*HH + h];      // coalesced across h
        pacc[t] = acc;
    }
    __syncthreads();
    if (t < HH) qsh[t] = pacc[t] + pacc[t + HH];
    __syncthreads();
    float4 qv = reinterpret_cast<float4*>(qsh)[lane];

    // ---- zero this block's w slice (1 store/thread; ordered via fence+atomic) ----
    wout[(size_t)(chunk*ROWS_PER_CHUNK + t)*BB + b] = 0.f;

    // ---- stream 8 groups of 4 rows; cheap halving reduction ----
    float rs[8];
    #pragma unroll
    for (int g = 0; g < 8; g++) {
        float s0 = ev[0].x*qv.x + ev[0].y*qv.y + ev[0].z*qv.z + ev[0].w*qv.w;
        float s1 = ev[1].x*qv.x + ev[1].y*qv.y + ev[1].z*qv.z + ev[1].w*qv.w;
        float s2 = ev[2].x*qv.x + ev[2].y*qv.y + ev[2].z*qv.z + ev[2].w*qv.w;
        float s3 = ev[3].x*qv.x + ev[3].y*qv.y + ev[3].z*qv.z + ev[3].w*qv.w;
        if (g < 7) {
            const float* nb = ebase + (size_t)(g+1)*4*rstride;
            #pragma unroll
            for (int j = 0; j < 4; j++)
                ev[j] = __ldcs(reinterpret_cast<const float4*>(nb + (size_t)j*rstride));
        }
        float r0 = comb(s0, s1, 16, lane);
        float r1 = comb(s2, s3, 16, lane);
        float v0 = comb(r0, r1, 8, lane);
        v0 += __shfl_xor_sync(0xffffffffu, v0, 4);
        v0 += __shfl_xor_sync(0xffffffffu, v0, 2);
        v0 += __shfl_xor_sync(0xffffffffu, v0, 1);
        rs[g] = v0;                 // one complete row-score per lane (x8 copies)
    }

    // warp (M, L) over its 32 rows
    float m = rs[0];
    #pragma unroll
    for (int g = 1; g < 8; g++) m = fmaxf(m, rs[g]);
    #pragma unroll
    for (int off = 16; off; off >>= 1)
        m = fmaxf(m, __shfl_xor_sync(0xffffffffu, m, off));
    float l = 0.f;
    #pragma unroll
    for (int g = 0; g < 8; g++) l += __expf(rs[g] - m);
    #pragma unroll
    for (int off = 16; off; off >>= 1)
        l += __shfl_xor_sync(0xffffffffu, l, off);
    l *= 0.125f;                     // each row counted exactly 8x

    if (lane == 0) { sm[warp] = m; sl[warp] = l; }
    __syncthreads();
    if (t == 0) {
        float M = sm[0];
        #pragma unroll
        for (int c = 1; c < 8; c++) M = fmaxf(M, sm[c]);
        float L = 0.f;
        #pragma unroll
        for (int c = 0; c < 8; c++) L += sl[c]*__expf(sm[c]-M);
        g_Mp[chunk*BB + b] = M;
        g_Lp[chunk*BB + b] = L;
        __threadfence();
        int old = atomicAdd(&g_cnt[b], 1);
        islast = (old == NCH-1);
        if (old == NCH-1) g_cnt[b] = 0;   // reset for next graph replay
    }
    __syncthreads();
    if (!islast) return;

    // ===================== finalize for this b (last block) =================
    __threadfence();

    // p_t = S * sigmoid(tanh(d@W_p)@v_p)  (only 128 blocks run this)
    {
        int h = t & 127, half = t >> 7;
        float acc = 0.f;
        #pragma unroll 16
        for (int k = half*64; k < half*64 + 64; k++)
            acc += dsh[k] * Wp[k*HH + h];
        pacc[t] = acc;
    }
    __syncthreads();
    if (t < HH) pacc[t] = tanhf(pacc[t] + pacc[t + HH]) * vp[t];
    __syncthreads();
    for (int off = HH/2; off > 0; off >>= 1) {
        if (t < off) pacc[t] += pacc[t+off];
        __syncthreads();
    }
    if (t == 0) {
        float z = pacc[0];
        ML[2] = (float)SS / (1.f + expf(-z));
    }

    // global (M, L) over NCH chunk partials (warp 0)
    if (warp == 0) {
        float mm = (lane < NCH) ? ((const volatile float*)g_Mp)[lane*BB + b] : -INFINITY;
        float ll = (lane < NCH) ? ((const volatile float*)g_Lp)[lane*BB + b] : 0.f;
        float M = mm;
        #pragma unroll
        for (int off = 16; off; off >>= 1)
            M = fmaxf(M, __shfl_xor_sync(0xffffffffu, M, off));
        float lc = ll*__expf(mm - M);
        #pragma unroll
        for (int off = 16; off; off >>= 1)
            lc += __shfl_xor_sync(0xffffffffu, lc, off);
        if (lane == 0) { ML[0] = M; ML[1] = lc; }
    }
    __syncthreads();

    // window candidates (uniform per block)
    float pt = ML[2];
    int sf = (int)floorf(pt);
    int cs[5]; int cnt = 0;
    #pragma unroll
    for (int ds = -2; ds <= 2; ds++) {
        int sidx = sf + ds;
        if (sidx < 0 || sidx >= SS) continue;
        float diff = pt - (float)sidx;
        if (fabsf(diff) <= 2.0f) cs[cnt++] = sidx;
    }

    // stage window rows into shared (parallel loads)
    for (int idx = t; idx < cnt*HH; idx += 256) {
        int i = idx >> 7, h = idx & 127;
        esh[i][h] = e[((size_t)cs[i]*BB + b)*HH + h];
    }
    if (t < HH) x[HH + t] = dsh[t];
    __syncthreads();

    // warp i: score of window row i
    if (warp < cnt) {
        float v = 0.f;
        #pragma unroll
        for (int j = 0; j < 4; j++)
            v += esh[warp][lane + 32*j] * qsh[lane + 32*j];
        #pragma unroll
        for (int off = 16; off; off >>= 1)
            v += __shfl_xor_sync(0xffffffffu, v, off);
        if (lane == 0) scr[warp] = v;
    }
    __syncthreads();

    if (t < cnt) {
        float diff = pt - (float)cs[t];
        float a = expf(scr[t] - ML[0]) / ML[1];
        float v = a * expf(-diff*diff*0.5f);
        wvals[t] = v;
        wout[(size_t)cs[t]*BB + b] = v;
    }
    __syncthreads();

    if (t < HH) {
        float ctx = 0.f;
        for (int i = 0; i < cnt; i++)
            ctx += esh[i][t] * wvals[i];
        x[t] = ctx;
    }
    __syncthreads();

    // output GEMM, 2-way k-split
    {
        int h = t & 127, part = t >> 7;
        const float* Wcp = Wc + (size_t)part*HH*HH;
        float acc = 0.f;
        #pragma unroll 16
        for (int k = 0; k < HH; k++)
            acc += x[part*HH + k] * Wcp[k*HH + h];
        pacc[t] = acc;
    }
    __syncthreads();
    if (t < HH)
        out[b*HH + t] = tanhf(pacc[t] + pacc[t + HH]);
}

// ---------------------------------------------------------------------------
extern "C" void kernel_launch(void* const* d_in, const int* in_sizes, int n_in,
                              void* d_out, int out_size) {
    const float* e  = (const float*)d_in[0];
    const float* d  = (const float*)d_in[1];
    const float* Wa = (const float*)d_in[2];
    const float* Wp = (const float*)d_in[3];
    const float* vp = (const float*)d_in[4];
    const float* Wc = (const float*)d_in[5];

    float* base = (float*)d_out;
    float* out_ptr;
    float* w_ptr;
    if (out_size >= BB*HH + SS*BB) {
        out_ptr = base;
        w_ptr   = base + BB*HH;
    } else if (out_size == SS*BB) {
        cudaGetSymbolAddress((void**)&out_ptr, g_out_scr);
        w_ptr = base;
    } else {
        out_ptr = base;
        cudaGetSymbolAddress((void**)&w_ptr, g_w_scr);
    }

    fused_kernel<<<dim3(NCH, BB), 256>>>(e, d, Wa, Wp, vp, Wc, out_ptr, w_ptr);
}

// round 17
// speedup vs baseline: 1.0423x; 1.0312x over previous
#include <cuda_runtime.h>
#include <stdint.h>
#include <math.h>

#define SS 4096
#define BB 128
#define HH 128
#define NCH 16
#define ROWS_PER_CHUNK (SS/NCH)   // 256 rows per block, 32 per warp
#define STAGE_BYTES 2048          // 4 rows x 512 B
#define WARP_RING_BYTES (4*STAGE_BYTES)   // 4-stage ring = 8 KB per warp
#define DYN_SMEM (8*WARP_RING_BYTES)      // 64 KB per block

// scratch (no allocation allowed)
__device__ float g_Mp[NCH*BB];
__device__ float g_Lp[NCH*BB];
__device__ int   g_cnt[BB];       // zero-init at load; reset by last block
__device__ float g_out_scr[BB*HH];
__device__ float g_w_scr[SS*BB];

// array-halving combine
__device__ __forceinline__ float comb(float a, float b, int off, int lane) {
    float keep = (lane & off) ? b : a;
    float send = (lane & off) ? a : b;
    return keep + __shfl_xor_sync(0xffffffffu, send, off);
}

__device__ __forceinline__ void cp16(unsigned int dst_smem, const void* src) {
    asm volatile("cp.async.cg.shared.global [%0], [%1], 16;"
                 :: "r"(dst_smem), "l"(src) : "memory");
}
__device__ __forceinline__ void cp_commit() {
    asm volatile("cp.async.commit_group;" ::: "memory");
}
template<int N> __device__ __forceinline__ void cp_wait() {
    asm volatile("cp.async.wait_group %0;" :: "n"(N) : "memory");
}

extern __shared__ char dynsm[];

__global__ void __launch_bounds__(256, 3)
fused_kernel(const float* __restrict__ e,
             const float* __restrict__ d,
             const float* __restrict__ Wa,
             const float* __restrict__ Wp,
             const float* __restrict__ vp,
             const float* __restrict__ Wc,
             float* __restrict__ out,
             float* __restrict__ wout) {
    int chunk = blockIdx.x, b = blockIdx.y;
    int t = threadIdx.x;
    int warp = t >> 5, lane = t & 31;

    __shared__ float dsh[HH];
    __shared__ float qsh[HH];
    __shared__ float pacc[2*HH];
    __shared__ float sm[8], sl[8];
    __shared__ float esh[5][HH];
    __shared__ float x[2*HH];
    __shared__ float scr[5];
    __shared__ float wvals[5];
    __shared__ float ML[3];
    __shared__ int islast;

    // per-warp staging ring in dynamic smem
    char* ring = dynsm + warp*WARP_RING_BYTES;
    unsigned int ring_u32 = (unsigned int)__cvta_generic_to_shared(ring);

    int R0 = chunk*ROWS_PER_CHUNK + warp*32;
    const char* ebase = (const char*)e + (((size_t)R0*BB + b)*HH)*4 + lane*16;
    const size_t rsb = (size_t)BB*HH*4;   // 64 KB row stride

    // issue stage g: rows 4g..4g+3, each lane copies its own 16 B per row
    auto issue = [&](int g) {
        const char* src = ebase + (size_t)g*4*rsb;
        unsigned int dst = ring_u32 + (unsigned int)((g & 3)*STAGE_BYTES) + lane*16;
        cp16(dst,            src);
        cp16(dst + 512,  src + rsb);
        cp16(dst + 1024, src + 2*rsb);
        cp16(dst + 1536, src + 3*rsb);
        cp_commit();
    };

    // ---- deep prefetch FIRST: 4 stages in flight before anything else ----
    issue(0); issue(1); issue(2); issue(3);

    // ---- in-block q = d[b]@W_a (L2-resident; latency covered by prefetch) ----
    if (t < HH) dsh[t] = d[b*HH + t];
    __syncthreads();
    {
        int h = t & 127, half = t >> 7;
        float acc = 0.f;
        #pragma unroll 16
        for (int k = half*64; k < half*64 + 64; k++)
            acc += dsh[k] * Wa[k*HH + h];      // coalesced across h
        pacc[t] = acc;
    }
    __syncthreads();
    if (t < HH) qsh[t] = pacc[t] + pacc[t + HH];
    __syncthreads();
    float4 qv = reinterpret_cast<float4*>(qsh)[lane];

    // ---- zero this block's w slice (ordered via fence+atomic before finalize) ----
    wout[(size_t)(chunk*ROWS_PER_CHUNK + t)*BB + b] = 0.f;

    // compute stage g from smem: lane reads only its own 16 B per row
    auto compute = [&](int g) -> float {
        const float4* buf = (const float4*)(ring + (g & 3)*STAGE_BYTES);
        float4 e0 = buf[lane];
        float4 e1 = buf[32 + lane];
        float4 e2 = buf[64 + lane];
        float4 e3 = buf[96 + lane];
        float s0 = e0.x*qv.x + e0.y*qv.y + e0.z*qv.z + e0.w*qv.w;
        float s1 = e1.x*qv.x + e1.y*qv.y + e1.z*qv.z + e1.w*qv.w;
        float s2 = e2.x*qv.x + e2.y*qv.y + e2.z*qv.z + e2.w*qv.w;
        float s3 = e3.x*qv.x + e3.y*qv.y + e3.z*qv.z + e3.w*qv.w;
        float r0 = comb(s0, s1, 16, lane);
        float r1 = comb(s2, s3, 16, lane);
        float v0 = comb(r0, r1, 8, lane);
        v0 += __shfl_xor_sync(0xffffffffu, v0, 4);
        v0 += __shfl_xor_sync(0xffffffffu, v0, 2);
        v0 += __shfl_xor_sync(0xffffffffu, v0, 1);
        return v0;   // full row score, 8 copies across lanes
    };

    float rs[8];
    cp_wait<3>(); rs[0] = compute(0); issue(4);
    cp_wait<3>(); rs[1] = compute(1); issue(5);
    cp_wait<3>(); rs[2] = compute(2); issue(6);
    cp_wait<3>(); rs[3] = compute(3); issue(7);
    cp_wait<3>(); rs[4] = compute(4);
    cp_wait<2>(); rs[5] = compute(5);
    cp_wait<1>(); rs[6] = compute(6);
    cp_wait<0>(); rs[7] = compute(7);

    // warp (M, L) over its 32 rows (each row counted 8x)
    float m = rs[0];
    #pragma unroll
    for (int g = 1; g < 8; g++) m = fmaxf(m, rs[g]);
    #pragma unroll
    for (int off = 16; off; off >>= 1)
        m = fmaxf(m, __shfl_xor_sync(0xffffffffu, m, off));
    float l = 0.f;
    #pragma unroll
    for (int g = 0; g < 8; g++) l += __expf(rs[g] - m);
    #pragma unroll
    for (int off = 16; off; off >>= 1)
        l += __shfl_xor_sync(0xffffffffu, l, off);
    l *= 0.125f;

    if (lane == 0) { sm[warp] = m; sl[warp] = l; }
    __syncthreads();
    if (t == 0) {
        float M = sm[0];
        #pragma unroll
        for (int c = 1; c < 8; c++) M = fmaxf(M, sm[c]);
        float L = 0.f;
        #pragma unroll
        for (int c = 0; c < 8; c++) L += sl[c]*__expf(sm[c]-M);
        g_Mp[chunk*BB + b] = M;
        g_Lp[chunk*BB + b] = L;
        __threadfence();
        int old = atomicAdd(&g_cnt[b], 1);
        islast = (old == NCH-1);
        if (old == NCH-1) g_cnt[b] = 0;   // reset for next graph replay
    }
    __syncthreads();
    if (!islast) return;

    // ===================== finalize for this b (last block) =================
    __threadfence();

    // p_t = S * sigmoid(tanh(d@W_p)@v_p)
    {
        int h = t & 127, half = t >> 7;
        float acc = 0.f;
        #pragma unroll 16
        for (int k = half*64; k < half*64 + 64; k++)
            acc += dsh[k] * Wp[k*HH + h];
        pacc[t] = acc;
    }
    __syncthreads();
    if (t < HH) pacc[t] = tanhf(pacc[t] + pacc[t + HH]) * vp[t];
    __syncthreads();
    for (int off = HH/2; off > 0; off >>= 1) {
        if (t < off) pacc[t] += pacc[t+off];
        __syncthreads();
    }
    if (t == 0) {
        float z = pacc[0];
        ML[2] = (float)SS / (1.f + expf(-z));
    }

    // global (M, L) over NCH chunk partials (warp 0)
    if (warp == 0) {
        float mm = (lane < NCH) ? ((const volatile float*)g_Mp)[lane*BB + b] : -INFINITY;
        float ll = (lane < NCH) ? ((const volatile float*)g_Lp)[lane*BB + b] : 0.f;
        float M = mm;
        #pragma unroll
        for (int off = 16; off; off >>= 1)
            M = fmaxf(M, __shfl_xor_sync(0xffffffffu, M, off));
        float lc = ll*__expf(mm - M);
        #pragma unroll
        for (int off = 16; off; off >>= 1)
            lc += __shfl_xor_sync(0xffffffffu, lc, off);
        if (lane == 0) { ML[0] = M; ML[1] = lc; }
    }
    __syncthreads();

    // window candidates (uniform per block)
    float pt = ML[2];
    int sf = (int)floorf(pt);
    int cs[5]; int cnt = 0;
    #pragma unroll
    for (int ds = -2; ds <= 2; ds++) {
        int sidx = sf + ds;
        if (sidx < 0 || sidx >= SS) continue;
        float diff = pt - (float)sidx;
        if (fabsf(diff) <= 2.0f) cs[cnt++] = sidx;
    }

    // stage window rows into shared (parallel loads)
    for (int idx = t; idx < cnt*HH; idx += 256) {
        int i = idx >> 7, h = idx & 127;
        esh[i][h] = e[((size_t)cs[i]*BB + b)*HH + h];
    }
    if (t < HH) x[HH + t] = dsh[t];
    __syncthreads();

    // warp i: score of window row i
    if (warp < cnt) {
        float v = 0.f;
        #pragma unroll
        for (int j = 0; j < 4; j++)
            v += esh[warp][lane + 32*j] * qsh[lane + 32*j];
        #pragma unroll
        for (int off = 16; off; off >>= 1)
            v += __shfl_xor_sync(0xffffffffu, v, off);
        if (lane == 0) scr[warp] = v;
    }
    __syncthreads();

    if (t < cnt) {
        float diff = pt - (float)cs[t];
        float a = expf(scr[t] - ML[0]) / ML[1];
        float v = a * expf(-diff*diff*0.5f);
        wvals[t] = v;
        wout[(size_t)cs[t]*BB + b] = v;
    }
    __syncthreads();

    if (t < HH) {
        float ctx = 0.f;
        for (int i = 0; i < cnt; i++)
            ctx += esh[i][t] * wvals[i];
        x[t] = ctx;
    }
    __syncthreads();

    // output GEMM, 2-way k-split
    {
        int h = t & 127, part = t >> 7;
        const float* Wcp = Wc + (size_t)part*HH*HH;
        float acc = 0.f;
        #pragma unroll 16
        for (int k = 0; k < HH; k++)
            acc += x[part*HH + k] * Wcp[k*HH + h];
        pacc[t] = acc;
    }
    __syncthreads();
    if (t < HH)
        out[b*HH + t] = tanhf(pacc[t] + pacc[t + HH]);
}

// ---------------------------------------------------------------------------
extern "C" void kernel_launch(void* const* d_in, const int* in_sizes, int n_in,
                              void* d_out, int out_size) {
    const float* e  = (const float*)d_in[0];
    const float* d  = (const float*)d_in[1];
    const float* Wa = (const float*)d_in[2];
    const float* Wp = (const float*)d_in[3];
    const float* vp = (const float*)d_in[4];
    const float* Wc = (const float*)d_in[5];

    float* base = (float*)d_out;
    float* out_ptr;
    float* w_ptr;
    if (out_size >= BB*HH + SS*BB) {
        out_ptr = base;
        w_ptr   = base + BB*HH;
    } else if (out_size == SS*BB) {
        cudaGetSymbolAddress((void**)&out_ptr, g_out_scr);
        w_ptr = base;
    } else {
        out_ptr = base;
        cudaGetSymbolAddress((void**)&w_ptr, g_w_scr);
    }

    // opt-in to 64 KB dynamic smem (host attribute set, not an allocation)
    cudaFuncSetAttribute(fused_kernel,
                         cudaFuncAttributeMaxDynamicSharedMemorySize, DYN_SMEM);

    fused_kernel<<<dim3(NCH, BB), 256, DYN_SMEM>>>(e, d, Wa, Wp, vp, Wc,
                                                   out_ptr, w_ptr);
}